// round 16
// baseline (speedup 1.0000x reference)
#include <cuda_runtime.h>
#include <cuda_bf16.h>
#include <math.h>
#include <stdint.h>

#define B     64
#define PP    128
#define DD    256
#define HH    256
#define FEAT  131072
#define M1    128
#define NROWS (B*512)           // 32768
#define KCHUNKS 256             // split-K chunks for mlp1 (512 K each)

#define STRA  20                // A-tile row stride (16 kpair words + 4 pad)
#define STRB  136               // B-tile row stride (128 cols + 8 pad)

#define SIMA_STG   5120
#define GEMM_STG   9472         // k_xw per stage (A 5120 + B 4352)
#define SXW_SMEM   75776        // merged kernel: max(simA 69632, xw 75776)

// k_bmm layout (words): A split 2x5120, B raw 2x4224 @10240, BHs @18688, BLs @20864
#define BMM_BRAW 10240
#define BMM_BHS  18688
#define BMM_BLS  20864
#define BMM_TOT  23040

// k_xw2 layout (words)
#define XW2_SAH  9216           // raw A: 2 x 4608 at 0
#define XW2_SAL  11776
#define XW2_B    14336          // B stages: 2 x 4352
#define XW2_TOT  23040

// k_mlp1 layout (words)
#define MLP_SAH  4608
#define MLP_SAL  5888
#define MLP_BRAW 7168
#define MLP_BHS  15616
#define MLP_BLS  17792
#define MLP_TOT  19968

// ---------------- scratch (device globals; no allocation) ----------------
__device__ float    g_invn[NROWS];
__device__ float    g_dinv[NROWS];
__device__ uint32_t g_Xh[(size_t)NROWS*128];
__device__ uint32_t g_Xl[(size_t)NROWS*128];
__device__ uint32_t g_Ah[(size_t)256*PP*64];
__device__ uint32_t g_Al[(size_t)256*PP*64];
__device__ uint32_t g_W1h[128*256], g_W1l[128*256];
__device__ uint32_t g_W2h[128*256], g_W2l[128*256];
__device__ float    g_XW[(size_t)NROWS*HH];        // raw fp32 XW + bias (unscaled)
__device__ float    g_Hb[(size_t)NROWS*HH];        // pre-BN h (fp32)
__device__ float    g_sum1[HH], g_sumsq1[HH], g_sum2[HH], g_sumsq2[HH];
__device__ float    g_Z1part[(size_t)KCHUNKS*B*M1];
__device__ float    g_z1[B*M1];

// ---------------- helpers ----------------
__device__ __forceinline__ void split2(float a, float b, uint32_t& h, uint32_t& l) {
    __nv_bfloat162 hb = __floats2bfloat162_rn(a, b);
    float2 hf = __bfloat1622float2(hb);
    __nv_bfloat162 lb = __floats2bfloat162_rn(a - hf.x, b - hf.y);
    h = *(uint32_t*)&hb;
    l = *(uint32_t*)&lb;
}
__device__ __forceinline__ void mma16(float* c, const uint32_t* a, const uint32_t* b) {
    asm volatile("mma.sync.aligned.m16n8k16.row.col.f32.bf16.bf16.f32 "
                 "{%0,%1,%2,%3}, {%4,%5,%6,%7}, {%8,%9}, {%0,%1,%2,%3};\n"
                 : "+f"(c[0]), "+f"(c[1]), "+f"(c[2]), "+f"(c[3])
                 : "r"(a[0]), "r"(a[1]), "r"(a[2]), "r"(a[3]),
                   "r"(b[0]), "r"(b[1]));
}
__device__ __forceinline__ void ldsm4(uint32_t* r, uint32_t addr) {
    asm volatile("ldmatrix.sync.aligned.m8n8.x4.shared.b16 {%0,%1,%2,%3}, [%4];"
                 : "=r"(r[0]), "=r"(r[1]), "=r"(r[2]), "=r"(r[3]) : "r"(addr));
}
__device__ __forceinline__ void ldsm2(uint32_t* r, uint32_t addr) {
    asm volatile("ldmatrix.sync.aligned.m8n8.x2.shared.b16 {%0,%1}, [%2];"
                 : "=r"(r[0]), "=r"(r[1]) : "r"(addr));
}
__device__ __forceinline__ void cpa(uint32_t* dst, const void* src) {
    uint32_t d = (uint32_t)__cvta_generic_to_shared(dst);
    asm volatile("cp.async.cg.shared.global [%0], [%1], 16;" :: "r"(d), "l"(src));
}
#define CP_COMMIT() asm volatile("cp.async.commit_group;")
#define CP_WAIT0()  asm volatile("cp.async.wait_group 0;")
#define CP_WAIT1()  asm volatile("cp.async.wait_group 1;")

// ---------------- prep: norms + x rowK split + BN zero; tail blocks split W1/W2 ----------------
__global__ void __launch_bounds__(256) k_prep(const float* __restrict__ x,
                                              const float* __restrict__ W1,
                                              const float* __restrict__ W2) {
    if (blockIdx.x >= NROWS/8) {
        int blk = blockIdx.x - NROWS/8;
        const float* W = (blk < 32) ? W1 : W2;
        uint32_t* Wh = (blk < 32) ? g_W1h : g_W2h;
        uint32_t* Wl = (blk < 32) ? g_W1l : g_W2l;
        int idx = (blk & 31) * 256 + threadIdx.x;
        int kp = idx >> 6, c = (idx & 63) * 4;
        float4 a = *(const float4*)&W[(2*kp)*256 + c];
        float4 b = *(const float4*)&W[(2*kp+1)*256 + c];
        uint4 H, L;
        split2(a.x, b.x, H.x, L.x);
        split2(a.y, b.y, H.y, L.y);
        split2(a.z, b.z, H.z, L.z);
        split2(a.w, b.w, H.w, L.w);
        *(uint4*)&Wh[kp*256 + c] = H;
        *(uint4*)&Wl[kp*256 + c] = L;
        return;
    }
    __shared__ float sX[8][260];
    int tid = threadIdx.x, w = tid >> 5, lane = tid & 31;
    if (blockIdx.x == 0) {
        g_sum1[tid] = 0.f; g_sumsq1[tid] = 0.f;
        g_sum2[tid] = 0.f; g_sumsq2[tid] = 0.f;
    }
    int row = blockIdx.x * 8 + w;
    const float* xr = x + (size_t)row * DD;
    float s = 0.f;
#pragma unroll
    for (int i = 0; i < 8; i++) {
        float v = xr[lane + 32*i];
        sX[w][lane + 32*i] = v;
        s += v*v;
    }
#pragma unroll
    for (int o = 16; o; o >>= 1) s += __shfl_xor_sync(0xffffffffu, s, o);
    if (lane == 0) g_invn[row] = 1.0f / fmaxf(sqrtf(s), 1e-12f);
    __syncthreads();
    {
        int tr = tid >> 5;
        int c0 = (tid & 31) * 8;
        uint4 H, L;
        split2(sX[tr][c0+0], sX[tr][c0+1], H.x, L.x);
        split2(sX[tr][c0+2], sX[tr][c0+3], H.y, L.y);
        split2(sX[tr][c0+4], sX[tr][c0+5], H.z, L.z);
        split2(sX[tr][c0+6], sX[tr][c0+7], H.w, L.w);
        size_t o = (size_t)(blockIdx.x*8 + tr)*128 + (c0 >> 1);
        *(uint4*)&g_Xh[o] = H;
        *(uint4*)&g_Xl[o] = L;
    }
}

// ---------------- merged: blocks [0,256) = simA; [256,768) = layer-1 XW tiles ----------------
__global__ void __launch_bounds__(256, 2) k_sxw(const float* __restrict__ mask,
                                                const uint32_t* __restrict__ Wh,
                                                const uint32_t* __restrict__ Wl,
                                                const float* __restrict__ bias) {
    extern __shared__ uint32_t S[];
    int tid = threadIdx.x, w = tid >> 5, lane = tid & 31, g = lane >> 2, t = lane & 3;
    int wm = w & 3, wn = w >> 2;
    int lrow = lane & 15, lhalf = lane >> 4;
    uint32_t sbase = (uint32_t)__cvta_generic_to_shared(S);

    if (blockIdx.x < 256) {
        // ======================= simA body =======================
        __shared__ float sInv[128];
        __shared__ float sdeg[128];
        int bn = blockIdx.x;
        int rowbase = bn * 128;
        int blrow = lane & 7, blhalf = (lane >> 3) & 1;
        if (tid < 128) { sInv[tid] = g_invn[rowbase + tid]; sdeg[tid] = 0.f; }

        float acc[2][8][4];
#pragma unroll
        for (int mi=0;mi<2;mi++)
#pragma unroll
            for (int ni=0;ni<8;ni++)
#pragma unroll
                for (int q=0;q<4;q++) acc[mi][ni][q] = 0.f;

#pragma unroll 1
        for (int pc = 0; pc < 2; pc++) {
            int st = (pc % 3) * SIMA_STG;
#pragma unroll
            for (int i2 = 0; i2 < 2; i2++) {
                int idx = tid + i2*256;
                int r = idx >> 2, q = (idx & 3) * 4;
                cpa(&S[st + r*STRA + q],        g_Xh + (size_t)(rowbase + r)*128 + pc*16 + q);
                cpa(&S[st + 2560 + r*STRA + q], g_Xl + (size_t)(rowbase + r)*128 + pc*16 + q);
            }
            CP_COMMIT();
        }
#pragma unroll 1
        for (int it = 0; it < 8; it++) {
            if (it < 7) { CP_WAIT1(); } else { CP_WAIT0(); }
            __syncthreads();
            if (it + 2 < 8) {
                int c = it + 2, st = (c % 3) * SIMA_STG;
#pragma unroll
                for (int i2 = 0; i2 < 2; i2++) {
                    int idx = tid + i2*256;
                    int r = idx >> 2, q = (idx & 3) * 4;
                    cpa(&S[st + r*STRA + q],        g_Xh + (size_t)(rowbase + r)*128 + c*16 + q);
                    cpa(&S[st + 2560 + r*STRA + q], g_Xl + (size_t)(rowbase + r)*128 + c*16 + q);
                }
                CP_COMMIT();
            }
            uint32_t stw = (uint32_t)((it % 3) * SIMA_STG);
#pragma unroll
            for (int kb = 0; kb < 16; kb += 8) {
                uint32_t ah[2][4], al[2][4];
#pragma unroll
                for (int mi=0;mi<2;mi++) {
                    uint32_t ad = sbase + ((stw + (uint32_t)((wm*32 + mi*16 + lrow)*STRA + kb + 4*lhalf)) << 2);
                    ldsm4(ah[mi], ad);
                    ldsm4(al[mi], ad + (2560u << 2));
                }
#pragma unroll
                for (int ni=0;ni<8;ni++) {
                    uint32_t bh[2], bl[2];
                    uint32_t bd = sbase + ((stw + (uint32_t)((wn*64 + ni*8 + blrow)*STRA + kb + 4*blhalf)) << 2);
                    ldsm2(bh, bd);
                    ldsm2(bl, bd + (2560u << 2));
#pragma unroll
                    for (int mi=0;mi<2;mi++) {
                        mma16(acc[mi][ni], ah[mi], bh);
                        mma16(acc[mi][ni], ah[mi], bl);
                        mma16(acc[mi][ni], al[mi], bh);
                    }
                }
            }
        }
        __syncthreads();

        uint32_t* Sh = S;            // 128 x 68
        uint32_t* Sl = S + 8704;
        float rs[2][2] = {{0.f, 0.f}, {0.f, 0.f}};
#pragma unroll
        for (int ni=0;ni<8;ni++) {
            int c0 = wn*64 + ni*8 + 2*t, c1 = c0 + 1;
            int cp = c0 >> 1;
            float ic0 = sInv[c0], ic1 = sInv[c1];
#pragma unroll
            for (int mi=0;mi<2;mi++) {
                int r0 = wm*32 + mi*16 + g, r1 = r0 + 8;
                float i0 = sInv[r0], i1 = sInv[r1];
                float v00 = (r0==c0) ? 1.f : (acc[mi][ni][0]*i0*ic0 + 1.f)*0.5f*mask[r0*PP+c0];
                float v01 = (r0==c1) ? 1.f : (acc[mi][ni][1]*i0*ic1 + 1.f)*0.5f*mask[r0*PP+c1];
                float v10 = (r1==c0) ? 1.f : (acc[mi][ni][2]*i1*ic0 + 1.f)*0.5f*mask[r1*PP+c0];
                float v11 = (r1==c1) ? 1.f : (acc[mi][ni][3]*i1*ic1 + 1.f)*0.5f*mask[r1*PP+c1];
                uint32_t h, l;
                split2(v00, v01, h, l);
                Sh[r0*68 + cp] = h; Sl[r0*68 + cp] = l;
                split2(v10, v11, h, l);
                Sh[r1*68 + cp] = h; Sl[r1*68 + cp] = l;
                rs[mi][0] += v00 + v01;
                rs[mi][1] += v10 + v11;
            }
        }
#pragma unroll
        for (int mi=0;mi<2;mi++) {
            atomicAdd(&sdeg[wm*32 + mi*16 + g],     rs[mi][0]);
            atomicAdd(&sdeg[wm*32 + mi*16 + g + 8], rs[mi][1]);
        }
        __syncthreads();
        {
            size_t abase = (size_t)bn * 8192;
#pragma unroll
            for (int i2 = 0; i2 < 8; i2++) {
                int idx = tid + i2*256;
                int r = idx >> 4, off = (idx & 15) * 4;
                *(uint4*)&g_Ah[abase + r*64 + off] = *(uint4*)&Sh[r*68 + off];
                *(uint4*)&g_Al[abase + r*64 + off] = *(uint4*)&Sl[r*68 + off];
            }
        }
        if (tid < 128) {
            float deg = sdeg[tid];
            g_dinv[rowbase + tid] = (deg > 0.f) ? rsqrtf(fmaxf(deg, 1e-12f)) : 0.f;
        }
        return;
    }

    // ======================= layer-1 XW body =======================
    {
        int idx0 = blockIdx.x - 256;          // 0..511
        int m0 = (idx0 >> 1) * 128, n0 = (idx0 & 1) * 128;

        float acc[2][8][4];
#pragma unroll
        for (int mi=0;mi<2;mi++)
#pragma unroll
            for (int ni=0;ni<8;ni++)
#pragma unroll
                for (int q=0;q<4;q++) acc[mi][ni][q] = 0.f;

        {
#pragma unroll
            for (int i2 = 0; i2 < 2; i2++) {
                int idx = tid + i2*256;
                int r = idx >> 2, q = (idx & 3) * 4;
                cpa(&S[r*STRA + q],        g_Xh + (size_t)(m0 + r)*128 + q);
                cpa(&S[2560 + r*STRA + q], g_Xl + (size_t)(m0 + r)*128 + q);
            }
#pragma unroll
            for (int i2 = 0; i2 < 2; i2++) {
                int idx = tid + i2*256;
                int kp = idx >> 5, cc = (idx & 31) * 4;
                cpa(&S[5120 + kp*STRB + cc],        Wh + (size_t)kp*256 + n0 + cc);
                cpa(&S[5120 + 2176 + kp*STRB + cc], Wl + (size_t)kp*256 + n0 + cc);
            }
            CP_COMMIT();
        }
#pragma unroll 1
        for (int it = 0; it < 8; it++) {
            CP_WAIT0();
            __syncthreads();
            if (it + 1 < 8) {
                int c = it + 1, st = (c & 1) * GEMM_STG;
#pragma unroll
                for (int i2 = 0; i2 < 2; i2++) {
                    int idx = tid + i2*256;
                    int r = idx >> 2, q = (idx & 3) * 4;
                    cpa(&S[st + r*STRA + q],        g_Xh + (size_t)(m0 + r)*128 + c*16 + q);
                    cpa(&S[st + 2560 + r*STRA + q], g_Xl + (size_t)(m0 + r)*128 + c*16 + q);
                }
#pragma unroll
                for (int i2 = 0; i2 < 2; i2++) {
                    int idx = tid + i2*256;
                    int kp = idx >> 5, cc = (idx & 31) * 4;
                    cpa(&S[st + 5120 + kp*STRB + cc],        Wh + (size_t)(c*16 + kp)*256 + n0 + cc);
                    cpa(&S[st + 5120 + 2176 + kp*STRB + cc], Wl + (size_t)(c*16 + kp)*256 + n0 + cc);
                }
                CP_COMMIT();
            }
            uint32_t stw = (uint32_t)((it & 1) * GEMM_STG);
            const uint32_t* BH = S + (it & 1) * GEMM_STG + 5120;
            const uint32_t* BL = BH + 2176;
#pragma unroll
            for (int kb = 0; kb < 16; kb += 8) {
                uint32_t ah[2][4], al[2][4];
#pragma unroll
                for (int mi=0;mi<2;mi++) {
                    uint32_t ad = sbase + ((stw + (uint32_t)((wm*32 + mi*16 + lrow)*STRA + kb + 4*lhalf)) << 2);
                    ldsm4(ah[mi], ad);
                    ldsm4(al[mi], ad + (2560u << 2));
                }
#pragma unroll
                for (int ni=0;ni<8;ni++) {
                    int cb = wn*64 + ni*8 + g;
                    uint32_t bh[2], bl[2];
                    bh[0] = BH[(kb+t  )*STRB + cb]; bl[0] = BL[(kb+t  )*STRB + cb];
                    bh[1] = BH[(kb+t+4)*STRB + cb]; bl[1] = BL[(kb+t+4)*STRB + cb];
#pragma unroll
                    for (int mi=0;mi<2;mi++) {
                        mma16(acc[mi][ni], ah[mi], bh);
                        mma16(acc[mi][ni], ah[mi], bl);
                        mma16(acc[mi][ni], al[mi], bh);
                    }
                }
            }
        }
        // epilogue: acc + bias -> smem -> coalesced fp32 writes to g_XW (unscaled)
        __syncthreads();
        float* stg = (float*)S;
#pragma unroll
        for (int mi=0;mi<2;mi++) {
            int r0 = wm*32 + mi*16 + g, r1 = r0 + 8;
#pragma unroll
            for (int ni=0;ni<8;ni++) {
                int c0 = wn*64 + ni*8 + 2*t;
                float b0 = bias[n0 + c0], b1 = bias[n0 + c0 + 1];
                *(float2*)&stg[r0*132 + c0] = make_float2(acc[mi][ni][0] + b0, acc[mi][ni][1] + b1);
                *(float2*)&stg[r1*132 + c0] = make_float2(acc[mi][ni][2] + b0, acc[mi][ni][3] + b1);
            }
        }
        __syncthreads();
        {
            int q = tid & 31;
            int wrow = tid >> 5;
#pragma unroll
            for (int i = 0; i < 16; i++) {
                int r = wrow + i*8;
                *(float4*)&g_XW[(size_t)(m0 + r)*HH + n0 + q*4] = *(float4*)&stg[r*132 + q*4];
            }
        }
    }
}

// ---------------- XW2 (layer 2): A = BN1+relu(g_Hb) split in-kernel; epi raw fp32 --------------
__global__ void __launch_bounds__(256, 2) k_xw2(const uint32_t* __restrict__ Wh,
                                                const uint32_t* __restrict__ Wl,
                                                const float* __restrict__ bias,
                                                const float* __restrict__ sumArr,
                                                const float* __restrict__ sqArr,
                                                const float* __restrict__ gam,
                                                const float* __restrict__ bet) {
    extern __shared__ uint32_t S[];   // XW2_TOT words
    __shared__ float sSc[256], sSh[256];
    int tid = threadIdx.x, w = tid >> 5, lane = tid & 31, g = lane >> 2, t = lane & 3;
    int wm = w & 3, wn = w >> 2;
    int lrow = lane & 15, lhalf = lane >> 4;
    uint32_t sbase = (uint32_t)__cvta_generic_to_shared(S);
    int m0 = blockIdx.y * 128, n0 = blockIdx.x * 128;
    {
        int c = tid;
        const float invn = 1.0f / (float)NROWS;
        float m = sumArr[c] * invn;
        float v = sqArr[c] * invn - m*m;
        float sc = gam[c] * rsqrtf(v + 1e-5f);
        sSc[c] = sc; sSh[c] = bet[c] - m*sc;
    }

    float acc[2][8][4];
#pragma unroll
    for (int mi=0;mi<2;mi++)
#pragma unroll
        for (int ni=0;ni<8;ni++)
#pragma unroll
            for (int q=0;q<4;q++) acc[mi][ni][q] = 0.f;

    {
#pragma unroll
        for (int i2 = 0; i2 < 4; i2++) {
            int idx = tid + i2*256;
            int r = idx >> 3, q = (idx & 7) * 4;
            cpa(&S[r*36 + q], (const uint32_t*)(g_Hb + (size_t)(m0 + r)*256 + q));
        }
#pragma unroll
        for (int i2 = 0; i2 < 2; i2++) {
            int idx = tid + i2*256;
            int kp = idx >> 5, cc = (idx & 31) * 4;
            cpa(&S[XW2_B + kp*STRB + cc],        Wh + (size_t)kp*256 + n0 + cc);
            cpa(&S[XW2_B + 2176 + kp*STRB + cc], Wl + (size_t)kp*256 + n0 + cc);
        }
        CP_COMMIT();
    }
#pragma unroll 1
    for (int it = 0; it < 8; it++) {
        CP_WAIT0();
        __syncthreads();
        if (it + 1 < 8) {
            int c = it + 1;
            int rawst = (c & 1) * 4608;
#pragma unroll
            for (int i2 = 0; i2 < 4; i2++) {
                int idx = tid + i2*256;
                int r = idx >> 3, q = (idx & 7) * 4;
                cpa(&S[rawst + r*36 + q], (const uint32_t*)(g_Hb + (size_t)(m0 + r)*256 + c*32 + q));
            }
            int bst = XW2_B + (c & 1) * 4352;
#pragma unroll
            for (int i2 = 0; i2 < 2; i2++) {
                int idx = tid + i2*256;
                int kp = idx >> 5, cc = (idx & 31) * 4;
                cpa(&S[bst + kp*STRB + cc],        Wh + (size_t)(c*16 + kp)*256 + n0 + cc);
                cpa(&S[bst + 2176 + kp*STRB + cc], Wl + (size_t)(c*16 + kp)*256 + n0 + cc);
            }
            CP_COMMIT();
        }
        {
            const float* raw = (const float*)(S + (it & 1) * 4608);
#pragma unroll
            for (int i2 = 0; i2 < 8; i2++) {
                int idx = tid + i2*256;
                int r = idx >> 4, cp = idx & 15;
                int col = it*32 + 2*cp;
                float a = fmaxf(fmaf(raw[r*36 + 2*cp],     sSc[col],   sSh[col]),   0.f);
                float b = fmaxf(fmaf(raw[r*36 + 2*cp + 1], sSc[col+1], sSh[col+1]), 0.f);
                uint32_t h, l;
                split2(a, b, h, l);
                S[XW2_SAH + r*STRA + cp] = h;
                S[XW2_SAL + r*STRA + cp] = l;
            }
        }
        __syncthreads();
        const uint32_t* BH = S + XW2_B + (it & 1) * 4352;
        const uint32_t* BL = BH + 2176;
#pragma unroll
        for (int kb = 0; kb < 16; kb += 8) {
            uint32_t ah[2][4], al[2][4];
#pragma unroll
            for (int mi=0;mi<2;mi++) {
                uint32_t ad = sbase + ((uint32_t)(XW2_SAH + (wm*32 + mi*16 + lrow)*STRA + kb + 4*lhalf) << 2);
                ldsm4(ah[mi], ad);
                ldsm4(al[mi], ad + (2560u << 2));
            }
#pragma unroll
            for (int ni=0;ni<8;ni++) {
                int cb = wn*64 + ni*8 + g;
                uint32_t bh[2], bl[2];
                bh[0] = BH[(kb+t  )*STRB + cb]; bl[0] = BL[(kb+t  )*STRB + cb];
                bh[1] = BH[(kb+t+4)*STRB + cb]; bl[1] = BL[(kb+t+4)*STRB + cb];
#pragma unroll
                for (int mi=0;mi<2;mi++) {
                    mma16(acc[mi][ni], ah[mi], bh);
                    mma16(acc[mi][ni], ah[mi], bl);
                    mma16(acc[mi][ni], al[mi], bh);
                }
            }
        }
    }
    __syncthreads();
    float* stg = (float*)S;
#pragma unroll
    for (int mi=0;mi<2;mi++) {
        int r0 = wm*32 + mi*16 + g, r1 = r0 + 8;
#pragma unroll
        for (int ni=0;ni<8;ni++) {
            int c0 = wn*64 + ni*8 + 2*t;
            float b0 = bias[n0 + c0], b1 = bias[n0 + c0 + 1];
            *(float2*)&stg[r0*132 + c0] = make_float2(acc[mi][ni][0] + b0, acc[mi][ni][1] + b1);
            *(float2*)&stg[r1*132 + c0] = make_float2(acc[mi][ni][2] + b0, acc[mi][ni][3] + b1);
        }
    }
    __syncthreads();
    {
        int q = tid & 31;
        int wrow = tid >> 5;
#pragma unroll
        for (int i = 0; i < 16; i++) {
            int r = wrow + i*8;
            *(float4*)&g_XW[(size_t)(m0 + r)*HH + n0 + q*4] = *(float4*)&stg[r*132 + q*4];
        }
    }
}

// ---------------- H = dinv_i * A(bn) @ (dinv_k * XW) ; B split+scale in fill ----------------
__global__ void __launch_bounds__(256, 2) k_bmm(float* __restrict__ sumArr,
                                                float* __restrict__ sqArr) {
    extern __shared__ uint32_t S[];   // BMM_TOT words
    __shared__ float sDv[128];
    __shared__ float sSum[128], sSq[128];
    int bn = blockIdx.y;
    int h0 = blockIdx.x * 128;
    int rowbase = bn * 128;
    int tid = threadIdx.x, w = tid >> 5, lane = tid & 31, g = lane >> 2, t = lane & 3;
    int wm = w & 3, wn = w >> 2;
    int lrow = lane & 15, lhalf = lane >> 4;
    uint32_t sbase = (uint32_t)__cvta_generic_to_shared(S);
    uint32_t* BHs = S + BMM_BHS;
    uint32_t* BLs = S + BMM_BLS;
    if (tid < 128) { sDv[tid] = g_dinv[rowbase + tid]; sSum[tid] = 0.f; sSq[tid] = 0.f; }

    float acc[2][8][4];
#pragma unroll
    for (int mi=0;mi<2;mi++)
#pragma unroll
        for (int ni=0;ni<8;ni++)
#pragma unroll
            for (int q=0;q<4;q++) acc[mi][ni][q] = 0.f;

    {   // chunk 0
#pragma unroll
        for (int i2 = 0; i2 < 2; i2++) {
            int idx = tid + i2*256;
            int r = idx >> 2, q = (idx & 3) * 4;
            cpa(&S[r*STRA + q],        g_Ah + ((size_t)bn*128 + r)*64 + q);
            cpa(&S[2560 + r*STRA + q], g_Al + ((size_t)bn*128 + r)*64 + q);
        }
#pragma unroll
        for (int i2 = 0; i2 < 4; i2++) {
            int idx = tid + i2*256;
            int rr = idx >> 5, cc = (idx & 31) * 4;
            cpa(&S[BMM_BRAW + rr*132 + cc], (const uint32_t*)(g_XW + (size_t)(rowbase + rr)*HH + h0 + cc));
        }
        CP_COMMIT();
    }
#pragma unroll 1
    for (int it = 0; it < 4; it++) {
        CP_WAIT0();
        __syncthreads();
        if (it + 1 < 4) {
            int c = it + 1, st = (c & 1) * SIMA_STG;
#pragma unroll
            for (int i2 = 0; i2 < 2; i2++) {
                int idx = tid + i2*256;
                int r = idx >> 2, q = (idx & 3) * 4;
                cpa(&S[st + r*STRA + q],        g_Ah + ((size_t)bn*128 + r)*64 + c*16 + q);
                cpa(&S[st + 2560 + r*STRA + q], g_Al + ((size_t)bn*128 + r)*64 + c*16 + q);
            }
            int bst = BMM_BRAW + (c & 1) * 4224;
#pragma unroll
            for (int i2 = 0; i2 < 4; i2++) {
                int idx = tid + i2*256;
                int rr = idx >> 5, cc = (idx & 31) * 4;
                cpa(&S[bst + rr*132 + cc], (const uint32_t*)(g_XW + (size_t)(rowbase + c*32 + rr)*HH + h0 + cc));
            }
            CP_COMMIT();
        }
        // split+scale B of chunk it
        {
            const float* rawB = (const float*)(S + BMM_BRAW + (it & 1) * 4224);
#pragma unroll
            for (int i2 = 0; i2 < 2; i2++) {
                int idx = tid + i2*256;
                int kp = idx >> 5, cc = (idx & 31) * 4;
                float dv0 = sDv[it*32 + 2*kp], dv1 = sDv[it*32 + 2*kp + 1];
                float4 u = *(const float4*)&rawB[(2*kp  )*132 + cc];
                float4 v = *(const float4*)&rawB[(2*kp+1)*132 + cc];
                uint4 H, L;
                split2(u.x*dv0, v.x*dv1, H.x, L.x);
                split2(u.y*dv0, v.y*dv1, H.y, L.y);
                split2(u.z*dv0, v.z*dv1, H.z, L.z);
                split2(u.w*dv0, v.w*dv1, H.w, L.w);
                *(uint4*)&BHs[kp*STRB + cc] = H;
                *(uint4*)&BLs[kp*STRB + cc] = L;
            }
        }
        __syncthreads();
        uint32_t stw = (uint32_t)((it & 1) * SIMA_STG);
#pragma unroll
        for (int kb = 0; kb < 16; kb += 8) {
            uint32_t ah[2][4], al[2][4];
#pragma unroll
            for (int mi=0;mi<2;mi++) {
                uint32_t ad = sbase + ((stw + (uint32_t)((wm*32 + mi*16 + lrow)*STRA + kb + 4*lhalf)) << 2);
                ldsm4(ah[mi], ad);
                ldsm4(al[mi], ad + (2560u << 2));
            }
#pragma unroll
            for (int ni=0;ni<8;ni++) {
                int cb = wn*64 + ni*8 + g;
                uint32_t bh[2], bl[2];
                bh[0] = BHs[(kb+t  )*STRB + cb]; bl[0] = BLs[(kb+t  )*STRB + cb];
                bh[1] = BHs[(kb+t+4)*STRB + cb]; bl[1] = BLs[(kb+t+4)*STRB + cb];
#pragma unroll
                for (int mi=0;mi<2;mi++) {
                    mma16(acc[mi][ni], ah[mi], bh);
                    mma16(acc[mi][ni], ah[mi], bl);
                    mma16(acc[mi][ni], al[mi], bh);
                }
            }
        }
    }
    __syncthreads();
    float* stg = (float*)S;
#pragma unroll
    for (int mi=0;mi<2;mi++) {
        int r0 = wm*32 + mi*16 + g, r1 = r0 + 8;
#pragma unroll
        for (int ni=0;ni<8;ni++) {
            int c0 = wn*64 + ni*8 + 2*t;
            *(float2*)&stg[r0*132 + c0] = make_float2(acc[mi][ni][0], acc[mi][ni][1]);
            *(float2*)&stg[r1*132 + c0] = make_float2(acc[mi][ni][2], acc[mi][ni][3]);
        }
    }
    __syncthreads();
    {
        int q = tid & 31;
        int wrow = tid >> 5;
        float cs[4] = {0.f, 0.f, 0.f, 0.f};
        float cq[4] = {0.f, 0.f, 0.f, 0.f};
#pragma unroll
        for (int i = 0; i < 16; i++) {
            int r = wrow + i*8;
            float dv = sDv[r];
            float4 v = *(float4*)&stg[r*132 + q*4];
            v.x *= dv; v.y *= dv; v.z *= dv; v.w *= dv;
            *(float4*)&g_Hb[(size_t)(rowbase + r)*HH + h0 + q*4] = v;
            cs[0] += v.x; cs[1] += v.y; cs[2] += v.z; cs[3] += v.w;
            cq[0] += v.x*v.x; cq[1] += v.y*v.y; cq[2] += v.z*v.z; cq[3] += v.w*v.w;
        }
#pragma unroll
        for (int j = 0; j < 4; j++) {
            atomicAdd(&sSum[q*4 + j], cs[j]);
            atomicAdd(&sSq[q*4 + j],  cq[j]);
        }
    }
    __syncthreads();
    if (tid < 128) {
        atomicAdd(&sumArr[h0 + tid], sSum[tid]);
        atomicAdd(&sqArr[h0 + tid],  sSq[tid]);
    }
}

// ---------------- split-K readout GEMM: A = BN2+relu(g_Hb) in-kernel; B = Wm1 in-kernel --------
__global__ void __launch_bounds__(256, 2) k_mlp1(const float* __restrict__ Wm1,
                                                 const float* __restrict__ sumArr,
                                                 const float* __restrict__ sqArr,
                                                 const float* __restrict__ gam,
                                                 const float* __restrict__ bet) {
    extern __shared__ uint32_t S[];   // MLP_TOT words
    __shared__ float sSc[256], sSh[256];
    int kc0 = blockIdx.x;
    int kbase = kc0 * 512;
    int tid = threadIdx.x, w = tid >> 5, lane = tid & 31, g = lane >> 2, t = lane & 3;
    int wm = w & 3, wn = w >> 2;
    int lrow = lane & 15, lhalf = lane >> 4;
    uint32_t sbase = (uint32_t)__cvta_generic_to_shared(S);
    uint32_t* BHs = S + MLP_BHS;
    uint32_t* BLs = S + MLP_BLS;
    {
        int c = tid;
        const float invn = 1.0f / (float)NROWS;
        float m = sumArr[c] * invn;
        float v = sqArr[c] * invn - m*m;
        float sc = gam[c] * rsqrtf(v + 1e-5f);
        sSc[c] = sc; sSh[c] = bet[c] - m*sc;
    }
    float acc[8][4];
#pragma unroll
    for (int ni=0;ni<8;ni++)
#pragma unroll
        for (int q=0;q<4;q++) acc[ni][q] = 0.f;

    {
#pragma unroll
        for (int i2 = 0; i2 < 2; i2++) {
            int idx = tid + i2*256;
            int r = idx >> 3, q = (idx & 7) * 4;
            cpa(&S[r*36 + q], (const uint32_t*)(g_Hb + (size_t)r*FEAT + kbase + q));
        }
#pragma unroll
        for (int i2 = 0; i2 < 4; i2++) {
            int idx = tid + i2*256;
            int rr = idx >> 5, cc = (idx & 31) * 4;
            cpa(&S[MLP_BRAW + rr*132 + cc], (const uint32_t*)(Wm1 + (size_t)(kbase + rr)*128 + cc));
        }
        CP_COMMIT();
    }
#pragma unroll 1
    for (int it = 0; it < 16; it++) {
        CP_WAIT0();
        __syncthreads();
        if (it + 1 < 16) {
            int c = it + 1;
            int rawst = (c & 1) * 2304;
#pragma unroll
            for (int i2 = 0; i2 < 2; i2++) {
                int idx = tid + i2*256;
                int r = idx >> 3, q = (idx & 7) * 4;
                cpa(&S[rawst + r*36 + q], (const uint32_t*)(g_Hb + (size_t)r*FEAT + kbase + c*32 + q));
            }
            int bst = MLP_BRAW + (c & 1) * 4224;
#pragma unroll
            for (int i2 = 0; i2 < 4; i2++) {
                int idx = tid + i2*256;
                int rr = idx >> 5, cc = (idx & 31) * 4;
                cpa(&S[bst + rr*132 + cc], (const uint32_t*)(Wm1 + (size_t)(kbase + c*32 + rr)*128 + cc));
            }
            CP_COMMIT();
        }
        {
            const float* rawA = (const float*)(S + (it & 1) * 2304);
#pragma unroll
            for (int i2 = 0; i2 < 4; i2++) {
                int idx = tid + i2*256;
                int r = idx >> 4, cp = idx & 15;
                int col = (it*32 + 2*cp) & 255;
                float a = fmaxf(fmaf(rawA[r*36 + 2*cp],     sSc[col],   sSh[col]),   0.f);
                float b = fmaxf(fmaf(rawA[r*36 + 2*cp + 1], sSc[col+1], sSh[col+1]), 0.f);
                uint32_t h, l;
                split2(a, b, h, l);
                S[MLP_SAH + r*STRA + cp] = h;
                S[MLP_SAL + r*STRA + cp] = l;
            }
            const float* rawB = (const float*)(S + MLP_BRAW + (it & 1) * 4224);
#pragma unroll
            for (int i2 = 0; i2 < 2; i2++) {
                int idx = tid + i2*256;
                int kp = idx >> 5, cc = (idx & 31) * 4;
                float4 u = *(const float4*)&rawB[(2*kp  )*132 + cc];
                float4 v = *(const float4*)&rawB[(2*kp+1)*132 + cc];
                uint4 H, L;
                split2(u.x, v.x, H.x, L.x);
                split2(u.y, v.y, H.y, L.y);
                split2(u.z, v.z, H.z, L.z);
                split2(u.w, v.w, H.w, L.w);
                *(uint4*)&BHs[kp*STRB + cc] = H;
                *(uint4*)&BLs[kp*STRB + cc] = L;
            }
        }
        __syncthreads();
#pragma unroll
        for (int kb = 0; kb < 16; kb += 8) {
            uint32_t ah[4], al[4];
            uint32_t ad = sbase + ((uint32_t)(MLP_SAH + (wm*16 + lrow)*STRA + kb + 4*lhalf) << 2);
            ldsm4(ah, ad);
            ldsm4(al, ad + (1280u << 2));
#pragma unroll
            for (int ni=0;ni<8;ni++) {
                int cb = wn*64 + ni*8 + g;
                uint32_t bh[2], bl[2];
                bh[0] = BHs[(kb+t  )*STRB + cb]; bl[0] = BLs[(kb+t  )*STRB + cb];
                bh[1] = BHs[(kb+t+4)*STRB + cb]; bl[1] = BLs[(kb+t+4)*STRB + cb];
                mma16(acc[ni], ah, bh);
                mma16(acc[ni], ah, bl);
                mma16(acc[ni], al, bh);
            }
        }
    }
    float* out = g_Z1part + (size_t)kc0 * (B*M1);
    int r0 = wm*16 + g, r1 = r0 + 8;
#pragma unroll
    for (int ni=0;ni<8;ni++) {
        int c0 = wn*64 + ni*8 + 2*t;
        *(float2*)&out[r0*M1 + c0] = make_float2(acc[ni][0], acc[ni][1]);
        *(float2*)&out[r1*M1 + c0] = make_float2(acc[ni][2], acc[ni][3]);
    }
}

__global__ void k_red(const float* __restrict__ bm1) {
    int o = blockIdx.x*256 + threadIdx.x;
    float s = bm1[o & 127];
    for (int kc = 0; kc < KCHUNKS; kc++) s += g_Z1part[(size_t)kc*(B*M1) + o];
    g_z1[o] = s;
}

// ---------------- head (exact fp32) ----------------
__global__ void __launch_bounds__(256) k_head(const float* __restrict__ gm1, const float* __restrict__ bem1,
                                              const float* __restrict__ Wm2, const float* __restrict__ bm2,
                                              const float* __restrict__ gm2, const float* __restrict__ bem2,
                                              const float* __restrict__ Wm3, const float* __restrict__ bm3,
                                              float* __restrict__ out) {
    __shared__ float sz1[64][128];
    __shared__ float sz2[64][64];
    int tid = threadIdx.x;

    if (tid < 128) {
        float s = 0.f, s2 = 0.f;
        for (int b = 0; b < 64; b++) { float v = g_z1[b*128 + tid]; s += v; s2 += v*v; }
        float m = s * (1.f/64.f), var = s2 * (1.f/64.f) - m*m;
        float sc = gm1[tid] * rsqrtf(var + 1e-5f);
        float sh = bem1[tid] - m*sc;
        for (int b = 0; b < 64; b++)
            sz1[b][tid] = fmaxf(fmaf(g_z1[b*128 + tid], sc, sh), 0.f);
    }
    __syncthreads();

    for (int o = tid; o < 4096; o += 256) {
        int b = o >> 6, j = o & 63;
        float s = bm2[j];
#pragma unroll 8
        for (int m = 0; m < 128; m++) s = fmaf(sz1[b][m], Wm2[m*64 + j], s);
        sz2[b][j] = s;
    }
    __syncthreads();

    if (tid < 64) {
        float s = 0.f, s2 = 0.f;
        for (int b = 0; b < 64; b++) { float v = sz2[b][tid]; s += v; s2 += v*v; }
        float m = s * (1.f/64.f), var = s2 * (1.f/64.f) - m*m;
        float sc = gm2[tid] * rsqrtf(var + 1e-5f);
        float sh = bem2[tid] - m*sc;
        for (int b = 0; b < 64; b++)
            sz2[b][tid] = fmaxf(fmaf(sz2[b][tid], sc, sh), 0.f);
    }
    __syncthreads();

    if (tid < 128) {
        int b = tid >> 1, c = tid & 1;
        float s = bm3[c];
#pragma unroll
        for (int j = 0; j < 64; j++) s = fmaf(sz2[b][j], Wm3[j*2 + c], s);
        out[b*2 + c] = s;
    }
}

// ---------------- launch ----------------
extern "C" void kernel_launch(void* const* d_in, const int* in_sizes, int n_in,
                              void* d_out, int out_size) {
    const float* x    = (const float*)d_in[0];
    const float* mask = (const float*)d_in[1];
    const float* W1   = (const float*)d_in[2];
    const float* b1   = (const float*)d_in[3];
    const float* g1   = (const float*)d_in[4];
    const float* be1  = (const float*)d_in[5];
    const float* W2   = (const float*)d_in[6];
    const float* b2   = (const float*)d_in[7];
    const float* g2   = (const float*)d_in[8];
    const float* be2  = (const float*)d_in[9];
    const float* Wm1  = (const float*)d_in[10];
    const float* bm1  = (const float*)d_in[11];
    const float* gm1  = (const float*)d_in[12];
    const float* bem1 = (const float*)d_in[13];
    const float* Wm2  = (const float*)d_in[14];
    const float* bm2  = (const float*)d_in[15];
    const float* gm2  = (const float*)d_in[16];
    const float* bem2 = (const float*)d_in[17];
    const float* Wm3  = (const float*)d_in[18];
    const float* bm3  = (const float*)d_in[19];
    float* out = (float*)d_out;

    static bool init = false;
    static uint32_t *pW1h, *pW1l, *pW2h, *pW2l;
    static float *pSum1, *pSq1, *pSum2, *pSq2;
    if (!init) {
        init = true;
        cudaFuncSetAttribute(k_sxw,  cudaFuncAttributeMaxDynamicSharedMemorySize, SXW_SMEM);
        cudaFuncSetAttribute(k_xw2,  cudaFuncAttributeMaxDynamicSharedMemorySize, XW2_TOT*4);
        cudaFuncSetAttribute(k_bmm,  cudaFuncAttributeMaxDynamicSharedMemorySize, BMM_TOT*4);
        cudaFuncSetAttribute(k_mlp1, cudaFuncAttributeMaxDynamicSharedMemorySize, MLP_TOT*4);
        cudaGetSymbolAddress((void**)&pW1h, g_W1h);
        cudaGetSymbolAddress((void**)&pW1l, g_W1l);
        cudaGetSymbolAddress((void**)&pW2h, g_W2h);
        cudaGetSymbolAddress((void**)&pW2l, g_W2l);
        cudaGetSymbolAddress((void**)&pSum1, g_sum1);
        cudaGetSymbolAddress((void**)&pSq1,  g_sumsq1);
        cudaGetSymbolAddress((void**)&pSum2, g_sum2);
        cudaGetSymbolAddress((void**)&pSq2,  g_sumsq2);
    }

    // prep (norms + x split + BN zero + W1/W2 split in tail blocks)
    k_prep<<<NROWS/8 + 64, 256>>>(x, W1, W2);

    // simA and layer-1 XW run concurrently in one grid
    k_sxw<<<768, 256, SXW_SMEM>>>(mask, pW1h, pW1l, b1);

    // GCN layer 1 aggregation (dinv applied to B in-fill)
    k_bmm<<<dim3(2, 256), 256, BMM_TOT*4>>>(pSum1, pSq1);

    // GCN layer 2 (BN1+relu in k_xw2 fill; XW raw)
    k_xw2<<<dim3(2, 256), 256, XW2_TOT*4>>>(pW2h, pW2l, b2, pSum1, pSq1, g1, be1);
    k_bmm<<<dim3(2, 256), 256, BMM_TOT*4>>>(pSum2, pSq2);

    // readout + head (BN2+relu in k_mlp1 fill)
    k_mlp1<<<KCHUNKS, 256, MLP_TOT*4>>>(Wm1, pSum2, pSq2, g2, be2);
    k_red<<<32, 256>>>(bm1);
    k_head<<<1, 256>>>(gm1, bem1, Wm2, bm2, gm2, bem2, Wm3, bm3, out);
}

// round 17
// speedup vs baseline: 1.0248x; 1.0248x over previous
#include <cuda_runtime.h>
#include <cuda_bf16.h>
#include <math.h>
#include <stdint.h>

#define B     64
#define PP    128
#define DD    256
#define HH    256
#define FEAT  131072
#define M1    128
#define NROWS (B*512)           // 32768
#define KCHUNKS 256             // split-K chunks for mlp1 (512 K each)

#define STRA  20                // A-tile row stride (16 kpair words + 4 pad)
#define STRB  136               // B-tile row stride (128 cols + 8 pad)

#define SIMA_STG   5120
#define GEMM_STG   9472         // per stage (A 5120 + B 4352)
#define SXW_SMEM   75776        // merged kernel: max(simA 3-stg 61440 / fp32 staging 67584, xw 75776)

// k_xw2 layout (words)
#define XW2_SAH  9216           // raw A: 2 x 4608 at 0
#define XW2_SAL  11776
#define XW2_B    14336          // B stages: 2 x 4352
#define XW2_TOT  23040

// k_mlp1 layout (words)
#define MLP_SAH  4608
#define MLP_SAL  5888
#define MLP_BRAW 7168
#define MLP_BHS  15616
#define MLP_BLS  17792
#define MLP_TOT  19968

// ---------------- scratch (device globals; no allocation) ----------------
__device__ float    g_invn[NROWS];
__device__ float    g_dinv[NROWS];
__device__ uint32_t g_Xh[(size_t)NROWS*128];
__device__ uint32_t g_Xl[(size_t)NROWS*128];
__device__ uint32_t g_Ah[(size_t)256*PP*64];       // A' = A*dinv_c, kpair packed
__device__ uint32_t g_Al[(size_t)256*PP*64];
__device__ uint32_t g_W1h[128*256], g_W1l[128*256];
__device__ uint32_t g_W2h[128*256], g_W2l[128*256];
__device__ uint32_t g_XWh[(size_t)(NROWS/2)*256];  // XW+bias (unscaled), kpairN packed
__device__ uint32_t g_XWl[(size_t)(NROWS/2)*256];
__device__ float    g_Hb[(size_t)NROWS*HH];        // pre-BN h (fp32)
__device__ float    g_sum1[HH], g_sumsq1[HH], g_sum2[HH], g_sumsq2[HH];
__device__ float    g_Z1part[(size_t)KCHUNKS*B*M1];
__device__ float    g_z1[B*M1];

// ---------------- helpers ----------------
__device__ __forceinline__ void split2(float a, float b, uint32_t& h, uint32_t& l) {
    __nv_bfloat162 hb = __floats2bfloat162_rn(a, b);
    float2 hf = __bfloat1622float2(hb);
    __nv_bfloat162 lb = __floats2bfloat162_rn(a - hf.x, b - hf.y);
    h = *(uint32_t*)&hb;
    l = *(uint32_t*)&lb;
}
__device__ __forceinline__ void mma16(float* c, const uint32_t* a, const uint32_t* b) {
    asm volatile("mma.sync.aligned.m16n8k16.row.col.f32.bf16.bf16.f32 "
                 "{%0,%1,%2,%3}, {%4,%5,%6,%7}, {%8,%9}, {%0,%1,%2,%3};\n"
                 : "+f"(c[0]), "+f"(c[1]), "+f"(c[2]), "+f"(c[3])
                 : "r"(a[0]), "r"(a[1]), "r"(a[2]), "r"(a[3]),
                   "r"(b[0]), "r"(b[1]));
}
__device__ __forceinline__ void ldsm4(uint32_t* r, uint32_t addr) {
    asm volatile("ldmatrix.sync.aligned.m8n8.x4.shared.b16 {%0,%1,%2,%3}, [%4];"
                 : "=r"(r[0]), "=r"(r[1]), "=r"(r[2]), "=r"(r[3]) : "r"(addr));
}
__device__ __forceinline__ void ldsm2(uint32_t* r, uint32_t addr) {
    asm volatile("ldmatrix.sync.aligned.m8n8.x2.shared.b16 {%0,%1}, [%2];"
                 : "=r"(r[0]), "=r"(r[1]) : "r"(addr));
}
__device__ __forceinline__ void cpa(uint32_t* dst, const void* src) {
    uint32_t d = (uint32_t)__cvta_generic_to_shared(dst);
    asm volatile("cp.async.cg.shared.global [%0], [%1], 16;" :: "r"(d), "l"(src));
}
#define CP_COMMIT() asm volatile("cp.async.commit_group;")
#define CP_WAIT0()  asm volatile("cp.async.wait_group 0;")
#define CP_WAIT1()  asm volatile("cp.async.wait_group 1;")

// ---------------- prep: norms + x rowK split + BN zero; tail blocks split W1/W2 ----------------
__global__ void __launch_bounds__(256) k_prep(const float* __restrict__ x,
                                              const float* __restrict__ W1,
                                              const float* __restrict__ W2) {
    if (blockIdx.x >= NROWS/8) {
        int blk = blockIdx.x - NROWS/8;
        const float* W = (blk < 32) ? W1 : W2;
        uint32_t* Wh = (blk < 32) ? g_W1h : g_W2h;
        uint32_t* Wl = (blk < 32) ? g_W1l : g_W2l;
        int idx = (blk & 31) * 256 + threadIdx.x;
        int kp = idx >> 6, c = (idx & 63) * 4;
        float4 a = *(const float4*)&W[(2*kp)*256 + c];
        float4 b = *(const float4*)&W[(2*kp+1)*256 + c];
        uint4 H, L;
        split2(a.x, b.x, H.x, L.x);
        split2(a.y, b.y, H.y, L.y);
        split2(a.z, b.z, H.z, L.z);
        split2(a.w, b.w, H.w, L.w);
        *(uint4*)&Wh[kp*256 + c] = H;
        *(uint4*)&Wl[kp*256 + c] = L;
        return;
    }
    __shared__ float sX[8][260];
    int tid = threadIdx.x, w = tid >> 5, lane = tid & 31;
    if (blockIdx.x == 0) {
        g_sum1[tid] = 0.f; g_sumsq1[tid] = 0.f;
        g_sum2[tid] = 0.f; g_sumsq2[tid] = 0.f;
    }
    int row = blockIdx.x * 8 + w;
    const float* xr = x + (size_t)row * DD;
    float s = 0.f;
#pragma unroll
    for (int i = 0; i < 8; i++) {
        float v = xr[lane + 32*i];
        sX[w][lane + 32*i] = v;
        s += v*v;
    }
#pragma unroll
    for (int o = 16; o; o >>= 1) s += __shfl_xor_sync(0xffffffffu, s, o);
    if (lane == 0) g_invn[row] = 1.0f / fmaxf(sqrtf(s), 1e-12f);
    __syncthreads();
    {
        int tr = tid >> 5;
        int c0 = (tid & 31) * 8;
        uint4 H, L;
        split2(sX[tr][c0+0], sX[tr][c0+1], H.x, L.x);
        split2(sX[tr][c0+2], sX[tr][c0+3], H.y, L.y);
        split2(sX[tr][c0+4], sX[tr][c0+5], H.z, L.z);
        split2(sX[tr][c0+6], sX[tr][c0+7], H.w, L.w);
        size_t o = (size_t)(blockIdx.x*8 + tr)*128 + (c0 >> 1);
        *(uint4*)&g_Xh[o] = H;
        *(uint4*)&g_Xl[o] = L;
    }
}

// ---------------- merged: blocks [0,256) = simA (A' = A*dinv_c); [256,768) = layer-1 XW ------
__global__ void __launch_bounds__(256, 2) k_sxw(const float* __restrict__ mask,
                                                const uint32_t* __restrict__ Wh,
                                                const uint32_t* __restrict__ Wl,
                                                const float* __restrict__ bias) {
    extern __shared__ uint32_t S[];
    int tid = threadIdx.x, w = tid >> 5, lane = tid & 31, g = lane >> 2, t = lane & 3;
    int wm = w & 3, wn = w >> 2;
    int lrow = lane & 15, lhalf = lane >> 4;
    uint32_t sbase = (uint32_t)__cvta_generic_to_shared(S);

    if (blockIdx.x < 256) {
        // ======================= simA body =======================
        __shared__ float sInv[128];
        __shared__ float sdeg[128];
        int bn = blockIdx.x;
        int rowbase = bn * 128;
        int blrow = lane & 7, blhalf = (lane >> 3) & 1;
        if (tid < 128) { sInv[tid] = g_invn[rowbase + tid]; sdeg[tid] = 0.f; }

        float acc[2][8][4];
#pragma unroll
        for (int mi=0;mi<2;mi++)
#pragma unroll
            for (int ni=0;ni<8;ni++)
#pragma unroll
                for (int q=0;q<4;q++) acc[mi][ni][q] = 0.f;

#pragma unroll 1
        for (int pc = 0; pc < 2; pc++) {
            int st = (pc % 3) * SIMA_STG;
#pragma unroll
            for (int i2 = 0; i2 < 2; i2++) {
                int idx = tid + i2*256;
                int r = idx >> 2, q = (idx & 3) * 4;
                cpa(&S[st + r*STRA + q],        g_Xh + (size_t)(rowbase + r)*128 + pc*16 + q);
                cpa(&S[st + 2560 + r*STRA + q], g_Xl + (size_t)(rowbase + r)*128 + pc*16 + q);
            }
            CP_COMMIT();
        }
#pragma unroll 1
        for (int it = 0; it < 8; it++) {
            if (it < 7) { CP_WAIT1(); } else { CP_WAIT0(); }
            __syncthreads();
            if (it + 2 < 8) {
                int c = it + 2, st = (c % 3) * SIMA_STG;
#pragma unroll
                for (int i2 = 0; i2 < 2; i2++) {
                    int idx = tid + i2*256;
                    int r = idx >> 2, q = (idx & 3) * 4;
                    cpa(&S[st + r*STRA + q],        g_Xh + (size_t)(rowbase + r)*128 + c*16 + q);
                    cpa(&S[st + 2560 + r*STRA + q], g_Xl + (size_t)(rowbase + r)*128 + c*16 + q);
                }
                CP_COMMIT();
            }
            uint32_t stw = (uint32_t)((it % 3) * SIMA_STG);
#pragma unroll
            for (int kb = 0; kb < 16; kb += 8) {
                uint32_t ah[2][4], al[2][4];
#pragma unroll
                for (int mi=0;mi<2;mi++) {
                    uint32_t ad = sbase + ((stw + (uint32_t)((wm*32 + mi*16 + lrow)*STRA + kb + 4*lhalf)) << 2);
                    ldsm4(ah[mi], ad);
                    ldsm4(al[mi], ad + (2560u << 2));
                }
#pragma unroll
                for (int ni=0;ni<8;ni++) {
                    uint32_t bh[2], bl[2];
                    uint32_t bd = sbase + ((stw + (uint32_t)((wn*64 + ni*8 + blrow)*STRA + kb + 4*blhalf)) << 2);
                    ldsm2(bh, bd);
                    ldsm2(bl, bd + (2560u << 2));
#pragma unroll
                    for (int mi=0;mi<2;mi++) {
                        mma16(acc[mi][ni], ah[mi], bh);
                        mma16(acc[mi][ni], ah[mi], bl);
                        mma16(acc[mi][ni], al[mi], bh);
                    }
                }
            }
        }
        __syncthreads();   // mainloop done; reuse S as fp32 staging [128][132]

        float* stgF = (float*)S;
        float rs[2][2] = {{0.f, 0.f}, {0.f, 0.f}};
#pragma unroll
        for (int ni=0;ni<8;ni++) {
            int c0 = wn*64 + ni*8 + 2*t, c1 = c0 + 1;
            float ic0 = sInv[c0], ic1 = sInv[c1];
#pragma unroll
            for (int mi=0;mi<2;mi++) {
                int r0 = wm*32 + mi*16 + g, r1 = r0 + 8;
                float i0 = sInv[r0], i1 = sInv[r1];
                float v00 = (r0==c0) ? 1.f : (acc[mi][ni][0]*i0*ic0 + 1.f)*0.5f*mask[r0*PP+c0];
                float v01 = (r0==c1) ? 1.f : (acc[mi][ni][1]*i0*ic1 + 1.f)*0.5f*mask[r0*PP+c1];
                float v10 = (r1==c0) ? 1.f : (acc[mi][ni][2]*i1*ic0 + 1.f)*0.5f*mask[r1*PP+c0];
                float v11 = (r1==c1) ? 1.f : (acc[mi][ni][3]*i1*ic1 + 1.f)*0.5f*mask[r1*PP+c1];
                *(float2*)&stgF[r0*132 + c0] = make_float2(v00, v01);
                *(float2*)&stgF[r1*132 + c0] = make_float2(v10, v11);
                rs[mi][0] += v00 + v01;
                rs[mi][1] += v10 + v11;
            }
        }
#pragma unroll
        for (int mi=0;mi<2;mi++) {
            atomicAdd(&sdeg[wm*32 + mi*16 + g],     rs[mi][0]);
            atomicAdd(&sdeg[wm*32 + mi*16 + g + 8], rs[mi][1]);
        }
        __syncthreads();
        if (tid < 128) {
            float deg = sdeg[tid];
            float dv = (deg > 0.f) ? rsqrtf(fmaxf(deg, 1e-12f)) : 0.f;
            sdeg[tid] = dv;
            g_dinv[rowbase + tid] = dv;
        }
        __syncthreads();
        {   // scale columns by dinv_c, split, coalesced write
            int q = tid & 31;
            int wrow = tid >> 5;
            float dv0 = sdeg[q*4], dv1 = sdeg[q*4+1], dv2 = sdeg[q*4+2], dv3 = sdeg[q*4+3];
            size_t abase = (size_t)bn * 8192;
#pragma unroll
            for (int i = 0; i < 16; i++) {
                int r = wrow + i*8;
                float4 v = *(float4*)&stgF[r*132 + q*4];
                uint2 H, L;
                split2(v.x*dv0, v.y*dv1, H.x, L.x);
                split2(v.z*dv2, v.w*dv3, H.y, L.y);
                *(uint2*)&g_Ah[abase + r*64 + q*2] = H;
                *(uint2*)&g_Al[abase + r*64 + q*2] = L;
            }
        }
        return;
    }

    // ======================= layer-1 XW body =======================
    {
        int idx0 = blockIdx.x - 256;          // 0..511
        int m0 = (idx0 >> 1) * 128, n0 = (idx0 & 1) * 128;

        float acc[2][8][4];
#pragma unroll
        for (int mi=0;mi<2;mi++)
#pragma unroll
            for (int ni=0;ni<8;ni++)
#pragma unroll
                for (int q=0;q<4;q++) acc[mi][ni][q] = 0.f;

        {
#pragma unroll
            for (int i2 = 0; i2 < 2; i2++) {
                int idx = tid + i2*256;
                int r = idx >> 2, q = (idx & 3) * 4;
                cpa(&S[r*STRA + q],        g_Xh + (size_t)(m0 + r)*128 + q);
                cpa(&S[2560 + r*STRA + q], g_Xl + (size_t)(m0 + r)*128 + q);
            }
#pragma unroll
            for (int i2 = 0; i2 < 2; i2++) {
                int idx = tid + i2*256;
                int kp = idx >> 5, cc = (idx & 31) * 4;
                cpa(&S[5120 + kp*STRB + cc],        Wh + (size_t)kp*256 + n0 + cc);
                cpa(&S[5120 + 2176 + kp*STRB + cc], Wl + (size_t)kp*256 + n0 + cc);
            }
            CP_COMMIT();
        }
#pragma unroll 1
        for (int it = 0; it < 8; it++) {
            CP_WAIT0();
            __syncthreads();
            if (it + 1 < 8) {
                int c = it + 1, st = (c & 1) * GEMM_STG;
#pragma unroll
                for (int i2 = 0; i2 < 2; i2++) {
                    int idx = tid + i2*256;
                    int r = idx >> 2, q = (idx & 3) * 4;
                    cpa(&S[st + r*STRA + q],        g_Xh + (size_t)(m0 + r)*128 + c*16 + q);
                    cpa(&S[st + 2560 + r*STRA + q], g_Xl + (size_t)(m0 + r)*128 + c*16 + q);
                }
#pragma unroll
                for (int i2 = 0; i2 < 2; i2++) {
                    int idx = tid + i2*256;
                    int kp = idx >> 5, cc = (idx & 31) * 4;
                    cpa(&S[st + 5120 + kp*STRB + cc],        Wh + (size_t)(c*16 + kp)*256 + n0 + cc);
                    cpa(&S[st + 5120 + 2176 + kp*STRB + cc], Wl + (size_t)(c*16 + kp)*256 + n0 + cc);
                }
                CP_COMMIT();
            }
            uint32_t stw = (uint32_t)((it & 1) * GEMM_STG);
            const uint32_t* BH = S + (it & 1) * GEMM_STG + 5120;
            const uint32_t* BL = BH + 2176;
#pragma unroll
            for (int kb = 0; kb < 16; kb += 8) {
                uint32_t ah[2][4], al[2][4];
#pragma unroll
                for (int mi=0;mi<2;mi++) {
                    uint32_t ad = sbase + ((stw + (uint32_t)((wm*32 + mi*16 + lrow)*STRA + kb + 4*lhalf)) << 2);
                    ldsm4(ah[mi], ad);
                    ldsm4(al[mi], ad + (2560u << 2));
                }
#pragma unroll
                for (int ni=0;ni<8;ni++) {
                    int cb = wn*64 + ni*8 + g;
                    uint32_t bh[2], bl[2];
                    bh[0] = BH[(kb+t  )*STRB + cb]; bl[0] = BL[(kb+t  )*STRB + cb];
                    bh[1] = BH[(kb+t+4)*STRB + cb]; bl[1] = BL[(kb+t+4)*STRB + cb];
#pragma unroll
                    for (int mi=0;mi<2;mi++) {
                        mma16(acc[mi][ni], ah[mi], bh);
                        mma16(acc[mi][ni], ah[mi], bl);
                        mma16(acc[mi][ni], al[mi], bh);
                    }
                }
            }
        }
        // epilogue: acc + bias -> smem -> split kpairN write (unscaled)
        __syncthreads();
        float* stg = (float*)S;
#pragma unroll
        for (int mi=0;mi<2;mi++) {
            int r0 = wm*32 + mi*16 + g, r1 = r0 + 8;
#pragma unroll
            for (int ni=0;ni<8;ni++) {
                int c0 = wn*64 + ni*8 + 2*t;
                float b0 = bias[n0 + c0], b1 = bias[n0 + c0 + 1];
                *(float2*)&stg[r0*132 + c0] = make_float2(acc[mi][ni][0] + b0, acc[mi][ni][1] + b1);
                *(float2*)&stg[r1*132 + c0] = make_float2(acc[mi][ni][2] + b0, acc[mi][ni][3] + b1);
            }
        }
        __syncthreads();
#pragma unroll
        for (int i2 = 0; i2 < 8; i2++) {
            int idx = tid + i2*256;
            int kp = idx >> 5, c = (idx & 31) * 4;
            float4 u = *(float4*)&stg[(2*kp  )*132 + c];
            float4 v = *(float4*)&stg[(2*kp+1)*132 + c];
            uint4 H, L;
            split2(u.x, v.x, H.x, L.x);
            split2(u.y, v.y, H.y, L.y);
            split2(u.z, v.z, H.z, L.z);
            split2(u.w, v.w, H.w, L.w);
            *(uint4*)&g_XWh[((size_t)(m0>>1) + kp)*256 + n0 + c] = H;
            *(uint4*)&g_XWl[((size_t)(m0>>1) + kp)*256 + n0 + c] = L;
        }
    }
}

// ---------------- XW2 (layer 2): A = BN1+relu(g_Hb) split in-kernel; epi split unscaled --------
__global__ void __launch_bounds__(256, 2) k_xw2(const uint32_t* __restrict__ Wh,
                                                const uint32_t* __restrict__ Wl,
                                                const float* __restrict__ bias,
                                                const float* __restrict__ sumArr,
                                                const float* __restrict__ sqArr,
                                                const float* __restrict__ gam,
                                                const float* __restrict__ bet) {
    extern __shared__ uint32_t S[];   // XW2_TOT words
    __shared__ float sSc[256], sSh[256];
    int tid = threadIdx.x, w = tid >> 5, lane = tid & 31, g = lane >> 2, t = lane & 3;
    int wm = w & 3, wn = w >> 2;
    int lrow = lane & 15, lhalf = lane >> 4;
    uint32_t sbase = (uint32_t)__cvta_generic_to_shared(S);
    int m0 = blockIdx.y * 128, n0 = blockIdx.x * 128;
    {
        int c = tid;
        const float invn = 1.0f / (float)NROWS;
        float m = sumArr[c] * invn;
        float v = sqArr[c] * invn - m*m;
        float sc = gam[c] * rsqrtf(v + 1e-5f);
        sSc[c] = sc; sSh[c] = bet[c] - m*sc;
    }

    float acc[2][8][4];
#pragma unroll
    for (int mi=0;mi<2;mi++)
#pragma unroll
        for (int ni=0;ni<8;ni++)
#pragma unroll
            for (int q=0;q<4;q++) acc[mi][ni][q] = 0.f;

    {
#pragma unroll
        for (int i2 = 0; i2 < 4; i2++) {
            int idx = tid + i2*256;
            int r = idx >> 3, q = (idx & 7) * 4;
            cpa(&S[r*36 + q], (const uint32_t*)(g_Hb + (size_t)(m0 + r)*256 + q));
        }
#pragma unroll
        for (int i2 = 0; i2 < 2; i2++) {
            int idx = tid + i2*256;
            int kp = idx >> 5, cc = (idx & 31) * 4;
            cpa(&S[XW2_B + kp*STRB + cc],        Wh + (size_t)kp*256 + n0 + cc);
            cpa(&S[XW2_B + 2176 + kp*STRB + cc], Wl + (size_t)kp*256 + n0 + cc);
        }
        CP_COMMIT();
    }
#pragma unroll 1
    for (int it = 0; it < 8; it++) {
        CP_WAIT0();
        __syncthreads();
        if (it + 1 < 8) {
            int c = it + 1;
            int rawst = (c & 1) * 4608;
#pragma unroll
            for (int i2 = 0; i2 < 4; i2++) {
                int idx = tid + i2*256;
                int r = idx >> 3, q = (idx & 7) * 4;
                cpa(&S[rawst + r*36 + q], (const uint32_t*)(g_Hb + (size_t)(m0 + r)*256 + c*32 + q));
            }
            int bst = XW2_B + (c & 1) * 4352;
#pragma unroll
            for (int i2 = 0; i2 < 2; i2++) {
                int idx = tid + i2*256;
                int kp = idx >> 5, cc = (idx & 31) * 4;
                cpa(&S[bst + kp*STRB + cc],        Wh + (size_t)(c*16 + kp)*256 + n0 + cc);
                cpa(&S[bst + 2176 + kp*STRB + cc], Wl + (size_t)(c*16 + kp)*256 + n0 + cc);
            }
            CP_COMMIT();
        }
        {
            const float* raw = (const float*)(S + (it & 1) * 4608);
#pragma unroll
            for (int i2 = 0; i2 < 8; i2++) {
                int idx = tid + i2*256;
                int r = idx >> 4, cp = idx & 15;
                int col = it*32 + 2*cp;
                float a = fmaxf(fmaf(raw[r*36 + 2*cp],     sSc[col],   sSh[col]),   0.f);
                float b = fmaxf(fmaf(raw[r*36 + 2*cp + 1], sSc[col+1], sSh[col+1]), 0.f);
                uint32_t h, l;
                split2(a, b, h, l);
                S[XW2_SAH + r*STRA + cp] = h;
                S[XW2_SAL + r*STRA + cp] = l;
            }
        }
        __syncthreads();
        const uint32_t* BH = S + XW2_B + (it & 1) * 4352;
        const uint32_t* BL = BH + 2176;
#pragma unroll
        for (int kb = 0; kb < 16; kb += 8) {
            uint32_t ah[2][4], al[2][4];
#pragma unroll
            for (int mi=0;mi<2;mi++) {
                uint32_t ad = sbase + ((uint32_t)(XW2_SAH + (wm*32 + mi*16 + lrow)*STRA + kb + 4*lhalf) << 2);
                ldsm4(ah[mi], ad);
                ldsm4(al[mi], ad + (2560u << 2));
            }
#pragma unroll
            for (int ni=0;ni<8;ni++) {
                int cb = wn*64 + ni*8 + g;
                uint32_t bh[2], bl[2];
                bh[0] = BH[(kb+t  )*STRB + cb]; bl[0] = BL[(kb+t  )*STRB + cb];
                bh[1] = BH[(kb+t+4)*STRB + cb]; bl[1] = BL[(kb+t+4)*STRB + cb];
#pragma unroll
                for (int mi=0;mi<2;mi++) {
                    mma16(acc[mi][ni], ah[mi], bh);
                    mma16(acc[mi][ni], ah[mi], bl);
                    mma16(acc[mi][ni], al[mi], bh);
                }
            }
        }
    }
    __syncthreads();
    float* stg = (float*)S;
#pragma unroll
    for (int mi=0;mi<2;mi++) {
        int r0 = wm*32 + mi*16 + g, r1 = r0 + 8;
#pragma unroll
        for (int ni=0;ni<8;ni++) {
            int c0 = wn*64 + ni*8 + 2*t;
            float b0 = bias[n0 + c0], b1 = bias[n0 + c0 + 1];
            *(float2*)&stg[r0*132 + c0] = make_float2(acc[mi][ni][0] + b0, acc[mi][ni][1] + b1);
            *(float2*)&stg[r1*132 + c0] = make_float2(acc[mi][ni][2] + b0, acc[mi][ni][3] + b1);
        }
    }
    __syncthreads();
#pragma unroll
    for (int i2 = 0; i2 < 8; i2++) {
        int idx = tid + i2*256;
        int kp = idx >> 5, c = (idx & 31) * 4;
        float4 u = *(float4*)&stg[(2*kp  )*132 + c];
        float4 v = *(float4*)&stg[(2*kp+1)*132 + c];
        uint4 H, L;
        split2(u.x, v.x, H.x, L.x);
        split2(u.y, v.y, H.y, L.y);
        split2(u.z, v.z, H.z, L.z);
        split2(u.w, v.w, H.w, L.w);
        *(uint4*)&g_XWh[((size_t)(m0>>1) + kp)*256 + n0 + c] = H;
        *(uint4*)&g_XWl[((size_t)(m0>>1) + kp)*256 + n0 + c] = L;
    }
}

// ---------------- H = dinv_r * (A' @ XWs) ; pure-copy fills; staged epi + stats ----------------
__global__ void __launch_bounds__(256, 2) k_bmm(float* __restrict__ sumArr,
                                                float* __restrict__ sqArr) {
    extern __shared__ uint32_t S[];   // 2 * GEMM_STG
    __shared__ float sDv[128];
    __shared__ float sSum[128], sSq[128];
    int bn = blockIdx.y;
    int h0 = blockIdx.x * 128;
    int rowbase = bn * 128;
    int tid = threadIdx.x, w = tid >> 5, lane = tid & 31, g = lane >> 2, t = lane & 3;
    int wm = w & 3, wn = w >> 2;
    int lrow = lane & 15, lhalf = lane >> 4;
    uint32_t sbase = (uint32_t)__cvta_generic_to_shared(S);
    if (tid < 128) { sDv[tid] = g_dinv[rowbase + tid]; sSum[tid] = 0.f; sSq[tid] = 0.f; }

    float acc[2][8][4];
#pragma unroll
    for (int mi=0;mi<2;mi++)
#pragma unroll
        for (int ni=0;ni<8;ni++)
#pragma unroll
            for (int q=0;q<4;q++) acc[mi][ni][q] = 0.f;

    {   // chunk 0
#pragma unroll
        for (int i2 = 0; i2 < 2; i2++) {
            int idx = tid + i2*256;
            int r = idx >> 2, q = (idx & 3) * 4;
            cpa(&S[r*STRA + q],        g_Ah + ((size_t)bn*128 + r)*64 + q);
            cpa(&S[2560 + r*STRA + q], g_Al + ((size_t)bn*128 + r)*64 + q);
        }
#pragma unroll
        for (int i2 = 0; i2 < 2; i2++) {
            int idx = tid + i2*256;
            int kp = idx >> 5, cc = (idx & 31) * 4;
            cpa(&S[5120 + kp*STRB + cc],        g_XWh + ((size_t)(bn*64) + kp)*256 + h0 + cc);
            cpa(&S[5120 + 2176 + kp*STRB + cc], g_XWl + ((size_t)(bn*64) + kp)*256 + h0 + cc);
        }
        CP_COMMIT();
    }
#pragma unroll 1
    for (int it = 0; it < 4; it++) {
        CP_WAIT0();
        __syncthreads();
        if (it + 1 < 4) {
            int c = it + 1, st = (c & 1) * GEMM_STG;
#pragma unroll
            for (int i2 = 0; i2 < 2; i2++) {
                int idx = tid + i2*256;
                int r = idx >> 2, q = (idx & 3) * 4;
                cpa(&S[st + r*STRA + q],        g_Ah + ((size_t)bn*128 + r)*64 + c*16 + q);
                cpa(&S[st + 2560 + r*STRA + q], g_Al + ((size_t)bn*128 + r)*64 + c*16 + q);
            }
#pragma unroll
            for (int i2 = 0; i2 < 2; i2++) {
                int idx = tid + i2*256;
                int kp = idx >> 5, cc = (idx & 31) * 4;
                cpa(&S[st + 5120 + kp*STRB + cc],        g_XWh + ((size_t)(bn*64) + c*16 + kp)*256 + h0 + cc);
                cpa(&S[st + 5120 + 2176 + kp*STRB + cc], g_XWl + ((size_t)(bn*64) + c*16 + kp)*256 + h0 + cc);
            }
            CP_COMMIT();
        }
        uint32_t stw = (uint32_t)((it & 1) * GEMM_STG);
        const uint32_t* BH = S + (it & 1) * GEMM_STG + 5120;
        const uint32_t* BL = BH + 2176;
#pragma unroll
        for (int kb = 0; kb < 16; kb += 8) {
            uint32_t ah[2][4], al[2][4];
#pragma unroll
            for (int mi=0;mi<2;mi++) {
                uint32_t ad = sbase + ((stw + (uint32_t)((wm*32 + mi*16 + lrow)*STRA + kb + 4*lhalf)) << 2);
                ldsm4(ah[mi], ad);
                ldsm4(al[mi], ad + (2560u << 2));
            }
#pragma unroll
            for (int ni=0;ni<8;ni++) {
                int cb = wn*64 + ni*8 + g;
                uint32_t bh[2], bl[2];
                bh[0] = BH[(kb+t  )*STRB + cb]; bl[0] = BL[(kb+t  )*STRB + cb];
                bh[1] = BH[(kb+t+4)*STRB + cb]; bl[1] = BL[(kb+t+4)*STRB + cb];
#pragma unroll
                for (int mi=0;mi<2;mi++) {
                    mma16(acc[mi][ni], ah[mi], bh);
                    mma16(acc[mi][ni], ah[mi], bl);
                    mma16(acc[mi][ni], al[mi], bh);
                }
            }
        }
    }
    __syncthreads();
    float* stg = (float*)S;
#pragma unroll
    for (int mi=0;mi<2;mi++) {
        int r0 = wm*32 + mi*16 + g, r1 = r0 + 8;
#pragma unroll
        for (int ni=0;ni<8;ni++) {
            int c0 = wn*64 + ni*8 + 2*t;
            *(float2*)&stg[r0*132 + c0] = make_float2(acc[mi][ni][0], acc[mi][ni][1]);
            *(float2*)&stg[r1*132 + c0] = make_float2(acc[mi][ni][2], acc[mi][ni][3]);
        }
    }
    __syncthreads();
    {
        int q = tid & 31;
        int wrow = tid >> 5;
        float cs[4] = {0.f, 0.f, 0.f, 0.f};
        float cq[4] = {0.f, 0.f, 0.f, 0.f};
#pragma unroll
        for (int i = 0; i < 16; i++) {
            int r = wrow + i*8;
            float dv = sDv[r];
            float4 v = *(float4*)&stg[r*132 + q*4];
            v.x *= dv; v.y *= dv; v.z *= dv; v.w *= dv;
            *(float4*)&g_Hb[(size_t)(rowbase + r)*HH + h0 + q*4] = v;
            cs[0] += v.x; cs[1] += v.y; cs[2] += v.z; cs[3] += v.w;
            cq[0] += v.x*v.x; cq[1] += v.y*v.y; cq[2] += v.z*v.z; cq[3] += v.w*v.w;
        }
#pragma unroll
        for (int j = 0; j < 4; j++) {
            atomicAdd(&sSum[q*4 + j], cs[j]);
            atomicAdd(&sSq[q*4 + j],  cq[j]);
        }
    }
    __syncthreads();
    if (tid < 128) {
        atomicAdd(&sumArr[h0 + tid], sSum[tid]);
        atomicAdd(&sqArr[h0 + tid],  sSq[tid]);
    }
}

// ---------------- split-K readout GEMM: A = BN2+relu(g_Hb) in-kernel; B = Wm1 in-kernel --------
__global__ void __launch_bounds__(256, 2) k_mlp1(const float* __restrict__ Wm1,
                                                 const float* __restrict__ sumArr,
                                                 const float* __restrict__ sqArr,
                                                 const float* __restrict__ gam,
                                                 const float* __restrict__ bet) {
    extern __shared__ uint32_t S[];   // MLP_TOT words
    __shared__ float sSc[256], sSh[256];
    int kc0 = blockIdx.x;
    int kbase = kc0 * 512;
    int tid = threadIdx.x, w = tid >> 5, lane = tid & 31, g = lane >> 2, t = lane & 3;
    int wm = w & 3, wn = w >> 2;
    int lrow = lane & 15, lhalf = lane >> 4;
    uint32_t sbase = (uint32_t)__cvta_generic_to_shared(S);
    uint32_t* BHs = S + MLP_BHS;
    uint32_t* BLs = S + MLP_BLS;
    {
        int c = tid;
        const float invn = 1.0f / (float)NROWS;
        float m = sumArr[c] * invn;
        float v = sqArr[c] * invn - m*m;
        float sc = gam[c] * rsqrtf(v + 1e-5f);
        sSc[c] = sc; sSh[c] = bet[c] - m*sc;
    }
    float acc[8][4];
#pragma unroll
    for (int ni=0;ni<8;ni++)
#pragma unroll
        for (int q=0;q<4;q++) acc[ni][q] = 0.f;

    {
#pragma unroll
        for (int i2 = 0; i2 < 2; i2++) {
            int idx = tid + i2*256;
            int r = idx >> 3, q = (idx & 7) * 4;
            cpa(&S[r*36 + q], (const uint32_t*)(g_Hb + (size_t)r*FEAT + kbase + q));
        }
#pragma unroll
        for (int i2 = 0; i2 < 4; i2++) {
            int idx = tid + i2*256;
            int rr = idx >> 5, cc = (idx & 31) * 4;
            cpa(&S[MLP_BRAW + rr*132 + cc], (const uint32_t*)(Wm1 + (size_t)(kbase + rr)*128 + cc));
        }
        CP_COMMIT();
    }
#pragma unroll 1
    for (int it = 0; it < 16; it++) {
        CP_WAIT0();
        __syncthreads();
        if (it + 1 < 16) {
            int c = it + 1;
            int rawst = (c & 1) * 2304;
#pragma unroll
            for (int i2 = 0; i2 < 2; i2++) {
                int idx = tid + i2*256;
                int r = idx >> 3, q = (idx & 7) * 4;
                cpa(&S[rawst + r*36 + q], (const uint32_t*)(g_Hb + (size_t)r*FEAT + kbase + c*32 + q));
            }
            int bst = MLP_BRAW + (c & 1) * 4224;
#pragma unroll
            for (int i2 = 0; i2 < 4; i2++) {
                int idx = tid + i2*256;
                int rr = idx >> 5, cc = (idx & 31) * 4;
                cpa(&S[bst + rr*132 + cc], (const uint32_t*)(Wm1 + (size_t)(kbase + c*32 + rr)*128 + cc));
            }
            CP_COMMIT();
        }
        {
            const float* rawA = (const float*)(S + (it & 1) * 2304);
#pragma unroll
            for (int i2 = 0; i2 < 4; i2++) {
                int idx = tid + i2*256;
                int r = idx >> 4, cp = idx & 15;
                int col = (it*32 + 2*cp) & 255;
                float a = fmaxf(fmaf(rawA[r*36 + 2*cp],     sSc[col],   sSh[col]),   0.f);
                float b = fmaxf(fmaf(rawA[r*36 + 2*cp + 1], sSc[col+1], sSh[col+1]), 0.f);
                uint32_t h, l;
                split2(a, b, h, l);
                S[MLP_SAH + r*STRA + cp] = h;
                S[MLP_SAL + r*STRA + cp] = l;
            }
            const float* rawB = (const float*)(S + MLP_BRAW + (it & 1) * 4224);
#pragma unroll
            for (int i2 = 0; i2 < 2; i2++) {
                int idx = tid + i2*256;
                int kp = idx >> 5, cc = (idx & 31) * 4;
                float4 u = *(const float4*)&rawB[(2*kp  )*132 + cc];
                float4 v = *(const float4*)&rawB[(2*kp+1)*132 + cc];
                uint4 H, L;
                split2(u.x, v.x, H.x, L.x);
                split2(u.y, v.y, H.y, L.y);
                split2(u.z, v.z, H.z, L.z);
                split2(u.w, v.w, H.w, L.w);
                *(uint4*)&BHs[kp*STRB + cc] = H;
                *(uint4*)&BLs[kp*STRB + cc] = L;
            }
        }
        __syncthreads();
#pragma unroll
        for (int kb = 0; kb < 16; kb += 8) {
            uint32_t ah[4], al[4];
            uint32_t ad = sbase + ((uint32_t)(MLP_SAH + (wm*16 + lrow)*STRA + kb + 4*lhalf) << 2);
            ldsm4(ah, ad);
            ldsm4(al, ad + (1280u << 2));
#pragma unroll
            for (int ni=0;ni<8;ni++) {
                int cb = wn*64 + ni*8 + g;
                uint32_t bh[2], bl[2];
                bh[0] = BHs[(kb+t  )*STRB + cb]; bl[0] = BLs[(kb+t  )*STRB + cb];
                bh[1] = BHs[(kb+t+4)*STRB + cb]; bl[1] = BLs[(kb+t+4)*STRB + cb];
                mma16(acc[ni], ah, bh);
                mma16(acc[ni], ah, bl);
                mma16(acc[ni], al, bh);
            }
        }
    }
    float* out = g_Z1part + (size_t)kc0 * (B*M1);
    int r0 = wm*16 + g, r1 = r0 + 8;
#pragma unroll
    for (int ni=0;ni<8;ni++) {
        int c0 = wn*64 + ni*8 + 2*t;
        *(float2*)&out[r0*M1 + c0] = make_float2(acc[ni][0], acc[ni][1]);
        *(float2*)&out[r1*M1 + c0] = make_float2(acc[ni][2], acc[ni][3]);
    }
}

__global__ void k_red(const float* __restrict__ bm1) {
    int o = blockIdx.x*256 + threadIdx.x;
    float s = bm1[o & 127];
    for (int kc = 0; kc < KCHUNKS; kc++) s += g_Z1part[(size_t)kc*(B*M1) + o];
    g_z1[o] = s;
}

// ---------------- head (exact fp32) ----------------
__global__ void __launch_bounds__(256) k_head(const float* __restrict__ gm1, const float* __restrict__ bem1,
                                              const float* __restrict__ Wm2, const float* __restrict__ bm2,
                                              const float* __restrict__ gm2, const float* __restrict__ bem2,
                                              const float* __restrict__ Wm3, const float* __restrict__ bm3,
                                              float* __restrict__ out) {
    __shared__ float sz1[64][128];
    __shared__ float sz2[64][64];
    int tid = threadIdx.x;

    if (tid < 128) {
        float s = 0.f, s2 = 0.f;
        for (int b = 0; b < 64; b++) { float v = g_z1[b*128 + tid]; s += v; s2 += v*v; }
        float m = s * (1.f/64.f), var = s2 * (1.f/64.f) - m*m;
        float sc = gm1[tid] * rsqrtf(var + 1e-5f);
        float sh = bem1[tid] - m*sc;
        for (int b = 0; b < 64; b++)
            sz1[b][tid] = fmaxf(fmaf(g_z1[b*128 + tid], sc, sh), 0.f);
    }
    __syncthreads();

    for (int o = tid; o < 4096; o += 256) {
        int b = o >> 6, j = o & 63;
        float s = bm2[j];
#pragma unroll 8
        for (int m = 0; m < 128; m++) s = fmaf(sz1[b][m], Wm2[m*64 + j], s);
        sz2[b][j] = s;
    }
    __syncthreads();

    if (tid < 64) {
        float s = 0.f, s2 = 0.f;
        for (int b = 0; b < 64; b++) { float v = sz2[b][tid]; s += v; s2 += v*v; }
        float m = s * (1.f/64.f), var = s2 * (1.f/64.f) - m*m;
        float sc = gm2[tid] * rsqrtf(var + 1e-5f);
        float sh = bem2[tid] - m*sc;
        for (int b = 0; b < 64; b++)
            sz2[b][tid] = fmaxf(fmaf(sz2[b][tid], sc, sh), 0.f);
    }
    __syncthreads();

    if (tid < 128) {
        int b = tid >> 1, c = tid & 1;
        float s = bm3[c];
#pragma unroll
        for (int j = 0; j < 64; j++) s = fmaf(sz2[b][j], Wm3[j*2 + c], s);
        out[b*2 + c] = s;
    }
}

// ---------------- launch ----------------
extern "C" void kernel_launch(void* const* d_in, const int* in_sizes, int n_in,
                              void* d_out, int out_size) {
    const float* x    = (const float*)d_in[0];
    const float* mask = (const float*)d_in[1];
    const float* W1   = (const float*)d_in[2];
    const float* b1   = (const float*)d_in[3];
    const float* g1   = (const float*)d_in[4];
    const float* be1  = (const float*)d_in[5];
    const float* W2   = (const float*)d_in[6];
    const float* b2   = (const float*)d_in[7];
    const float* g2   = (const float*)d_in[8];
    const float* be2  = (const float*)d_in[9];
    const float* Wm1  = (const float*)d_in[10];
    const float* bm1  = (const float*)d_in[11];
    const float* gm1  = (const float*)d_in[12];
    const float* bem1 = (const float*)d_in[13];
    const float* Wm2  = (const float*)d_in[14];
    const float* bm2  = (const float*)d_in[15];
    const float* gm2  = (const float*)d_in[16];
    const float* bem2 = (const float*)d_in[17];
    const float* Wm3  = (const float*)d_in[18];
    const float* bm3  = (const float*)d_in[19];
    float* out = (float*)d_out;

    static bool init = false;
    static uint32_t *pW1h, *pW1l, *pW2h, *pW2l;
    static float *pSum1, *pSq1, *pSum2, *pSq2;
    if (!init) {
        init = true;
        cudaFuncSetAttribute(k_sxw,  cudaFuncAttributeMaxDynamicSharedMemorySize, SXW_SMEM);
        cudaFuncSetAttribute(k_xw2,  cudaFuncAttributeMaxDynamicSharedMemorySize, XW2_TOT*4);
        cudaFuncSetAttribute(k_bmm,  cudaFuncAttributeMaxDynamicSharedMemorySize, 2*GEMM_STG*4);
        cudaFuncSetAttribute(k_mlp1, cudaFuncAttributeMaxDynamicSharedMemorySize, MLP_TOT*4);
        cudaGetSymbolAddress((void**)&pW1h, g_W1h);
        cudaGetSymbolAddress((void**)&pW1l, g_W1l);
        cudaGetSymbolAddress((void**)&pW2h, g_W2h);
        cudaGetSymbolAddress((void**)&pW2l, g_W2l);
        cudaGetSymbolAddress((void**)&pSum1, g_sum1);
        cudaGetSymbolAddress((void**)&pSq1,  g_sumsq1);
        cudaGetSymbolAddress((void**)&pSum2, g_sum2);
        cudaGetSymbolAddress((void**)&pSq2,  g_sumsq2);
    }

    // prep (norms + x split + BN zero + W1/W2 split in tail blocks)
    k_prep<<<NROWS/8 + 64, 256>>>(x, W1, W2);

    // simA (A' = A*dinv_c) and layer-1 XW (split, unscaled) run concurrently
    k_sxw<<<768, 256, SXW_SMEM>>>(mask, pW1h, pW1l, b1);

    // GCN layer 1 aggregation (pure-copy fills, dinv_r in epilogue)
    k_bmm<<<dim3(2, 256), 256, 2*GEMM_STG*4>>>(pSum1, pSq1);

    // GCN layer 2 (BN1+relu in k_xw2 fill; XW split unscaled)
    k_xw2<<<dim3(2, 256), 256, XW2_TOT*4>>>(pW2h, pW2l, b2, pSum1, pSq1, g1, be1);
    k_bmm<<<dim3(2, 256), 256, 2*GEMM_STG*4>>>(pSum2, pSq2);

    // readout + head (BN2+relu in k_mlp1 fill)
    k_mlp1<<<KCHUNKS, 256, MLP_TOT*4>>>(Wm1, pSum2, pSq2, g2, be2);
    k_red<<<32, 256>>>(bm1);
    k_head<<<1, 256>>>(gm1, bem1, Wm2, bm2, gm2, bem2, Wm3, bm3, out);
}